// round 12
// baseline (speedup 1.0000x reference)
#include <cuda_runtime.h>

#define BATCH 256
#define SEQ   2048
#define EMBD  16
#define HIDD  32
#define GATE  128

typedef unsigned long long u64;
typedef unsigned int       u32;

// Split input projection: (i,f) and (g,o) halves, float2 per (token, hid)
__device__ float2 g_zxIF[(size_t)BATCH * SEQ * HIDD];
__device__ float2 g_zxGO[(size_t)BATCH * SEQ * HIDD];

__device__ __forceinline__ u64 pack2(float lo, float hi){
    u64 r; asm("mov.b64 %0, {%1,%2};" : "=l"(r) : "f"(lo), "f"(hi)); return r;
}
__device__ __forceinline__ void unpack2(u64 v, float& lo, float& hi){
    asm("mov.b64 {%0,%1}, %2;" : "=f"(lo), "=f"(hi) : "l"(v));
}
__device__ __forceinline__ u64 ffma2(u64 a, u64 b, u64 c){
    u64 d; asm("fma.rn.f32x2 %0, %1, %2, %3;" : "=l"(d) : "l"(a), "l"(b), "l"(c)); return d;
}
__device__ __forceinline__ float tanha(float x){
    float y; asm("tanh.approx.f32 %0, %1;" : "=f"(y) : "f"(x)); return y;
}
// sigmoid(z) = 0.5 + 0.5*tanh(z/2)
__device__ __forceinline__ float sigt(float z){
    return fmaf(0.5f, tanha(0.5f * z), 0.5f);
}
__device__ __forceinline__ u32 smem_u32(const void* p){
    u32 a;
    asm("{ .reg .u64 t; cvta.to.shared.u64 t, %1; cvt.u32.u64 %0, t; }"
        : "=r"(a) : "l"(p));
    return a;
}
__device__ __forceinline__ void sts32(u32 addr, float v){
    asm volatile("st.shared.f32 [%0], %1;" :: "r"(addr), "f"(v) : "memory");
}
__device__ __forceinline__ void sts64(u32 addr, float a, float b){
    asm volatile("st.shared.v2.f32 [%0], {%1,%2};" :: "r"(addr), "f"(a), "f"(b) : "memory");
}
__device__ __forceinline__ float2 lds64(u32 addr){
    float2 v;
    asm volatile("ld.shared.v2.f32 {%0,%1}, [%2];"
        : "=f"(v.x), "=f"(v.y) : "r"(addr));
    return v;
}
__device__ __forceinline__ float4 lds128(u32 addr){
    float4 v;
    asm volatile("ld.shared.v4.f32 {%0,%1,%2,%3}, [%4];"
        : "=f"(v.x), "=f"(v.y), "=f"(v.z), "=f"(v.w) : "r"(addr));
    return v;
}
__device__ __forceinline__ void named_bar(int id){
    asm volatile("bar.sync %0, 64;" :: "r"(id) : "memory");
}

// ─────────────── Phase 1: zx halves = emb[tok]@Wk + b ───────────────────────
__global__ __launch_bounds__(256) void proj_kernel(
    const int*   __restrict__ tokens,
    const float* __restrict__ emb,
    const float* __restrict__ Wk,
    const float* __restrict__ bias)
{
    const int j    = threadIdx.x & 31;
    const int warp = (blockIdx.x << 3) + (threadIdx.x >> 5);
    const int base = warp << 8;

    u64 wk_if[EMBD], wk_go[EMBD];
    #pragma unroll
    for (int e = 0; e < EMBD; e++){
        wk_if[e] = pack2(Wk[e*GATE + j],      Wk[e*GATE + j + 32]);
        wk_go[e] = pack2(Wk[e*GATE + j + 64], Wk[e*GATE + j + 96]);
    }
    const u64 b_if = pack2(bias[j],      bias[j + 32]);
    const u64 b_go = pack2(bias[j + 64], bias[j + 96]);

    for (int s = 0; s < 256; s += 2){
        const int tflat = base + s + (j >> 4);
        const int tok   = tokens[tflat];
        const float xv  = emb[tok * EMBD + (j & 15)];

        u64 aI = b_if, aG = b_go;
        u64 cI = b_if, cG = b_go;
        #pragma unroll
        for (int e = 0; e < EMBD; e++){
            float xa = __shfl_sync(0xffffffffu, xv, e);
            float xb = __shfl_sync(0xffffffffu, xv, 16 + e);
            u64 xa2 = pack2(xa, xa);
            u64 xb2 = pack2(xb, xb);
            aI = ffma2(xa2, wk_if[e], aI);
            aG = ffma2(xa2, wk_go[e], aG);
            cI = ffma2(xb2, wk_if[e], cI);
            cG = ffma2(xb2, wk_go[e], cG);
        }
        float2 ifA, goA, ifB, goB;
        unpack2(aI, ifA.x, ifA.y); unpack2(aG, goA.x, goA.y);
        unpack2(cI, ifB.x, ifB.y); unpack2(cG, goB.x, goB.y);
        g_zxIF[(size_t)(base + s)     * HIDD + j] = ifA;
        g_zxGO[(size_t)(base + s)     * HIDD + j] = goA;
        g_zxIF[(size_t)(base + s + 1) * HIDD + j] = ifB;
        g_zxGO[(size_t)(base + s + 1) * HIDD + j] = goB;
    }
}

// ─────────────── Phase 2: gate-split recurrence, 2 warps per sequence ───────
// Warp r=0 owns gates (i,f), r=1 owns (g,o); lane j owns hid j -> 64 FFMA per
// lane per step (128-cycle floor, half of R11). Exchange: STS.64 of the two
// activated gates -> one named barrier -> LDS.64 of partner pair. Both warps
// combine redundantly; each keeps a PRIVATE h copy in smem (same-warp in-order
// STS->LDS, no second barrier). Gate buffer double-buffered by t-parity.
// Spill-proof: named scalar rings, hand-unrolled 4x, constant indices only.
#define CHAIN4S(acc, hh, ww, base)                      \
    acc = fmaf((hh).x, ww[(base)  ], acc);              \
    acc = fmaf((hh).y, ww[(base)+1], acc);              \
    acc = fmaf((hh).z, ww[(base)+2], acc);              \
    acc = fmaf((hh).w, ww[(base)+3], acc);

#define LSTM_BODY(Z, TK, tt, BUF)                                       \
{                                                                       \
    const float2 z2  = Z;                                               \
    const int    tok = TK;                                              \
    const int    pidx = min((tt) + 4, SEQ - 1);                         \
    Z  = zp[(size_t)pidx * HIDD];                                       \
    TK = tptr[pidx];                                                    \
    const float4 h0 = lds128(hbase +   0u);                             \
    const float4 h1 = lds128(hbase +  16u);                             \
    const float4 h2 = lds128(hbase +  32u);                             \
    const float4 h3 = lds128(hbase +  48u);                             \
    const float4 h4 = lds128(hbase +  64u);                             \
    const float4 h5 = lds128(hbase +  80u);                             \
    const float4 h6 = lds128(hbase +  96u);                             \
    const float4 h7 = lds128(hbase + 112u);                             \
    float a00 = z2.x, a10 = z2.y;                                       \
    float a01 = 0.f,  a11 = 0.f;                                        \
    CHAIN4S(a00, h0, wA, 0)   CHAIN4S(a10, h0, wB, 0)                   \
    CHAIN4S(a00, h1, wA, 4)   CHAIN4S(a10, h1, wB, 4)                   \
    CHAIN4S(a00, h2, wA, 8)   CHAIN4S(a10, h2, wB, 8)                   \
    CHAIN4S(a00, h3, wA,12)   CHAIN4S(a10, h3, wB,12)                   \
    CHAIN4S(a01, h4, wA,16)   CHAIN4S(a11, h4, wB,16)                   \
    CHAIN4S(a01, h5, wA,20)   CHAIN4S(a11, h5, wB,20)                   \
    CHAIN4S(a01, h6, wA,24)   CHAIN4S(a11, h6, wB,24)                   \
    CHAIN4S(a01, h7, wA,28)   CHAIN4S(a11, h7, wB,28)                   \
    const float za = a00 + a01;                                         \
    const float zb = a10 + a11;                                         \
    const float aa = fmaf(s_act, tanha(s_act * za), o_act);             \
    const float ab = sigt(zb);                                          \
    sts64(gw_addr + (BUF) * GBUF_STRIDE, aa, ab);                       \
    named_bar(bar_id);                                                  \
    const float2 po = lds64(gr_addr + (BUF) * GBUF_STRIDE);             \
    const float gi = r ? po.x : aa;                                     \
    const float gf = r ? po.y : ab;                                     \
    const float gg = r ? aa   : po.x;                                   \
    const float go = r ? ab   : po.y;                                   \
    const float cn = fmaf(gf, c, gi * gg);                              \
    const float hn = go * tanha(cn);                                    \
    const bool  m  = (tok != 0);                                        \
    c = m ? cn : c;                                                     \
    h = m ? hn : h;                                                     \
    sts32(haddr, h);                                                    \
    if (r == 0) optr[(size_t)(tt) * HIDD] = h;                          \
}

#define GBUF_STRIDE (2 * HIDD * 8)   // bytes per gate buffer (2 warps x 32 x float2)

__global__ __launch_bounds__(128) void rec_kernel(
    const int*   __restrict__ tokens,
    const float* __restrict__ Wr,
    float*       __restrict__ out)
{
    // [seq][r][hid] private h copies; [seq][buf][r][j] float2 gate exchange
    __shared__ float  hsw[2][2][HIDD];
    __shared__ float2 sg[2][2][2][HIDD];

    const int wlin = threadIdx.x >> 5;
    const int j    = threadIdx.x & 31;
    const int seq  = wlin >> 1;          // 0..1 local sequence
    const int r    = wlin & 1;           // 0: (i,f)  1: (g,o)
    const int b    = blockIdx.x * 2 + seq;
    const int bar_id = seq + 1;

    // weights for this warp's 2 gates: colA = j + r*64, colB = colA + 32
    const int colA = j + (r << 6);
    float wA[HIDD], wB[HIDD];
    #pragma unroll
    for (int k = 0; k < HIDD; k++){
        wA[k] = Wr[k*GATE + colA];
        wB[k] = Wr[k*GATE + colA + 32];
    }
    // gate a0 activation: r0 -> sigmoid(i), r1 -> tanh(g); a1 always sigmoid
    const float s_act = r ? 1.0f : 0.5f;
    const float o_act = r ? 0.0f : 0.5f;

    const float2* __restrict__ zp =
        (r ? g_zxGO : g_zxIF) + (size_t)b * SEQ * HIDD + j;
    const int* __restrict__ tptr = tokens + b * SEQ;
    float* optr = out + (size_t)b * SEQ * HIDD + j;

    const u32 hbase   = smem_u32(hsw[seq][r]);
    const u32 haddr   = hbase + (u32)j * 4u;
    const u32 sgbase  = smem_u32(sg[seq]);
    const u32 gw_addr = sgbase + (u32)((r      * HIDD + j) * 8);
    const u32 gr_addr = sgbase + (u32)(((1-r)  * HIDD + j) * 8);

    float2 zA = zp[0*HIDD], zB = zp[1*HIDD], zC = zp[2*HIDD], zD = zp[3*HIDD];
    int    tA = tptr[0],    tB = tptr[1],    tC = tptr[2],    tD = tptr[3];

    sts32(haddr, 0.0f);
    float h = 0.0f, c = 0.0f;

    for (int t = 0; t < SEQ; t += 4){
        LSTM_BODY(zA, tA, t + 0, 0)
        LSTM_BODY(zB, tB, t + 1, 1)
        LSTM_BODY(zC, tC, t + 2, 0)
        LSTM_BODY(zD, tD, t + 3, 1)
    }
}

extern "C" void kernel_launch(void* const* d_in, const int* in_sizes, int n_in,
                              void* d_out, int out_size)
{
    (void)in_sizes; (void)n_in; (void)out_size;
    const int*   tokens = (const int*)  d_in[0];
    const float* emb    = (const float*)d_in[1];
    const float* Wk     = (const float*)d_in[2];
    const float* Wr     = (const float*)d_in[3];
    const float* bias   = (const float*)d_in[4];
    float* out = (float*)d_out;

    proj_kernel<<<BATCH, 256>>>(tokens, emb, Wk, bias);
    rec_kernel<<<BATCH / 2, 128>>>(tokens, Wr, out);
}